// round 3
// baseline (speedup 1.0000x reference)
#include <cuda_runtime.h>
#include <cuda_bf16.h>
#include <cstdint>
#include <math.h>

#define B_  2
#define T_  2048
#define C_  1024
#define H_  16
#define HD_ 64
#define NBH_ (B_*H_)     // 32
#define M_   (B_*T_)     // 4096

// Scratch (allocation-free: __device__ globals)
__device__ float g_Q[(size_t)NBH_ * T_ * HD_];
__device__ float g_K[(size_t)NBH_ * T_ * HD_];
__device__ float g_V[(size_t)NBH_ * T_ * HD_];
__device__ float g_Y[(size_t)M_ * C_];

// ---------------------------------------------------------------------------
// bf16 hi/lo split helpers (x ~= hi + lo, |lo| <~ 2^-8 |x|)
// ---------------------------------------------------------------------------
__device__ __forceinline__ void splitf(float x, uint16_t& h, uint16_t& l) {
    __nv_bfloat16 hb = __float2bfloat16(x);
    __nv_bfloat16 lb = __float2bfloat16(x - __bfloat162float(hb));
    h = *reinterpret_cast<uint16_t*>(&hb);
    l = *reinterpret_cast<uint16_t*>(&lb);
}
__device__ __forceinline__ void split2(float x, float y, uint32_t& hi, uint32_t& lo) {
    uint16_t hx, lx, hy, ly;
    splitf(x, hx, lx); splitf(y, hy, ly);
    hi = (uint32_t)hx | ((uint32_t)hy << 16);
    lo = (uint32_t)lx | ((uint32_t)ly << 16);
}

#define LDSM4(r0, r1, r2, r3, addr) \
    asm volatile("ldmatrix.sync.aligned.m8n8.x4.shared.b16 {%0,%1,%2,%3}, [%4];" \
        : "=r"(r0), "=r"(r1), "=r"(r2), "=r"(r3) : "r"(addr))

#define MMA_BF16(d, a, b) \
    asm volatile("mma.sync.aligned.m16n8k16.row.col.f32.bf16.bf16.f32 " \
        "{%0,%1,%2,%3},{%4,%5,%6,%7},{%8,%9},{%0,%1,%2,%3};" \
        : "+f"((d)[0]), "+f"((d)[1]), "+f"((d)[2]), "+f"((d)[3]) \
        : "r"((a)[0]), "r"((a)[1]), "r"((a)[2]), "r"((a)[3]), \
          "r"((b)[0]), "r"((b)[1]))

// ---------------------------------------------------------------------------
// Epilogue scatter
// ---------------------------------------------------------------------------
template<int MODE>
__device__ __forceinline__ void emit(int m, int n, float val,
                                     const float* __restrict__ bias,
                                     float* __restrict__ out) {
    val += bias[n];
    if (MODE == 0) {
        const int bb = m >> 11;     // / T_
        const int t  = m & 2047;
        if (n < C_) {
            const int h = n >> 6, d = n & 63;
            g_Q[(((size_t)(bb*H_ + h))*T_ + t)*HD_ + d] = val * 0.125f;
        } else if (n < 2*C_) {
            const int nn = n - C_;
            const int h = nn >> 6, d = nn & 63;
            g_K[(((size_t)(bb*H_ + h))*T_ + t)*HD_ + d] = val;
        } else {
            const int nn = n - 2*C_;
            const int h = nn >> 6, d = nn & 63;
            g_V[(((size_t)(bb*H_ + h))*T_ + t)*HD_ + d] = val;
        }
    } else {
        out[(size_t)m * C_ + n] = val;
    }
}

// ---------------------------------------------------------------------------
// Tensor-core GEMM (bf16 3-term split, fp32 accum):
//   C[M, NCOLS] = A[M,1024] @ W[1024,NCOLS] + bias
// CTA 128x128, 8 warps (2x4), warp tile 64x32, k-chunk 16, double-buffered.
// smem planes per stage: Ahi/Alo [128][24], Bt_hi/Bt_lo [128][24] (Bt[n][k]).
// Row pad = 24 bf16 (48B) -> conflict-free ldmatrix phases.
// ---------------------------------------------------------------------------
#define ROWP 24
#define PLANE (128*ROWP)           // uint16 elements per plane
static const int GEMM_SMEM = 2 * 4 * PLANE * (int)sizeof(uint16_t);  // 49152 B

template<int NCOLS, int MODE>
__global__ void __launch_bounds__(256) gemm_bf16(const float* __restrict__ A,
                                                 const float* __restrict__ W,
                                                 const float* __restrict__ bias,
                                                 float* __restrict__ out) {
    extern __shared__ __align__(16) uint16_t sm16[];
    const int tid  = threadIdx.x;
    const int lane = tid & 31, wid = tid >> 5;
    const int wm = wid >> 2, wn = wid & 3;            // warps 2 x 4
    const int m0 = blockIdx.y * 128, n0 = blockIdx.x * 128;
    const float* Ap = (MODE == 0) ? A : (const float*)g_Y;

    // plane: 0=Ahi 1=Alo 2=Bhi 3=Blo
    uint16_t* pl[2][4];
    #pragma unroll
    for (int s = 0; s < 2; s++)
        #pragma unroll
        for (int p = 0; p < 4; p++)
            pl[s][p] = sm16 + (s*4 + p) * PLANE;

    // loader indices
    const int arow = tid >> 1, akq = (tid & 1) * 8;   // A: row 0..127, k 0 or 8
    const int br0 = tid >> 5,        bc0 = (tid & 31) * 4;          // B row 0..7
    const int br1 = (tid + 256) >> 5, bc1 = bc0;                    // B row 8..15
    const float* aptr = Ap + (size_t)(m0 + arow) * 1024 + akq;

    // ldmatrix lane addressing (row = lane&15, col = (lane>>4)*8)
    const int lrow = lane & 15, lcol = (lane >> 4) * 8;

    float acc[4][4][4];
    #pragma unroll
    for (int mt = 0; mt < 4; mt++)
        #pragma unroll
        for (int nt = 0; nt < 4; nt++)
            #pragma unroll
            for (int e = 0; e < 4; e++) acc[mt][nt][e] = 0.0f;

    // ---- prologue: stage 0 <- k=0 ----
    {
        const float4 av0 = *(const float4*)(aptr);
        const float4 av1 = *(const float4*)(aptr + 4);
        const float4 bv0 = *(const float4*)(W + (size_t)br0 * NCOLS + n0 + bc0);
        const float4 bv1 = *(const float4*)(W + (size_t)br1 * NCOLS + n0 + bc1);
        uint32_t h[4], l[4];
        split2(av0.x, av0.y, h[0], l[0]); split2(av0.z, av0.w, h[1], l[1]);
        split2(av1.x, av1.y, h[2], l[2]); split2(av1.z, av1.w, h[3], l[3]);
        *(uint4*)&pl[0][0][arow*ROWP + akq] = make_uint4(h[0], h[1], h[2], h[3]);
        *(uint4*)&pl[0][1][arow*ROWP + akq] = make_uint4(l[0], l[1], l[2], l[3]);
        const float bx[8] = {bv0.x, bv0.y, bv0.z, bv0.w, bv1.x, bv1.y, bv1.z, bv1.w};
        #pragma unroll
        for (int u = 0; u < 4; u++) {
            uint16_t hh, ll;
            splitf(bx[u], hh, ll);
            pl[0][2][(bc0 + u)*ROWP + br0] = hh;
            pl[0][3][(bc0 + u)*ROWP + br0] = ll;
            splitf(bx[4 + u], hh, ll);
            pl[0][2][(bc1 + u)*ROWP + br1] = hh;
            pl[0][3][(bc1 + u)*ROWP + br1] = ll;
        }
    }
    __syncthreads();

    const uint32_t sm_base = (uint32_t)__cvta_generic_to_shared(sm16);

    for (int it = 0; it < 64; it++) {
        const int s = it & 1;
        const bool pf = (it + 1) < 64;

        // ---- issue prefetch LDGs for next k-chunk ----
        float4 av0, av1, bv0, bv1;
        if (pf) {
            const int k0 = (it + 1) * 16;
            av0 = *(const float4*)(aptr + k0);
            av1 = *(const float4*)(aptr + k0 + 4);
            bv0 = *(const float4*)(W + (size_t)(k0 + br0) * NCOLS + n0 + bc0);
            bv1 = *(const float4*)(W + (size_t)(k0 + br1) * NCOLS + n0 + bc1);
        }

        // ---- compute from stage s ----
        const uint32_t base_ah = sm_base + (uint32_t)(s*4 + 0) * PLANE * 2;
        const uint32_t base_al = sm_base + (uint32_t)(s*4 + 1) * PLANE * 2;
        const uint32_t base_bh = sm_base + (uint32_t)(s*4 + 2) * PLANE * 2;
        const uint32_t base_bl = sm_base + (uint32_t)(s*4 + 3) * PLANE * 2;

        uint32_t bhi[4][2], blo[4][2];
        #pragma unroll
        for (int j = 0; j < 2; j++) {
            const uint32_t off = (uint32_t)((wn*32 + j*16 + lrow)*ROWP + lcol) * 2;
            uint32_t r0, r1, r2, r3;
            LDSM4(r0, r1, r2, r3, base_bh + off);
            bhi[2*j][0] = r0; bhi[2*j][1] = r2;
            bhi[2*j+1][0] = r1; bhi[2*j+1][1] = r3;
            LDSM4(r0, r1, r2, r3, base_bl + off);
            blo[2*j][0] = r0; blo[2*j][1] = r2;
            blo[2*j+1][0] = r1; blo[2*j+1][1] = r3;
        }

        uint32_t af[4][4];
        #pragma unroll
        for (int mt = 0; mt < 4; mt++) {
            const uint32_t off = (uint32_t)((wm*64 + mt*16 + lrow)*ROWP + lcol) * 2;
            LDSM4(af[mt][0], af[mt][1], af[mt][2], af[mt][3], base_ah + off);
        }
        #pragma unroll
        for (int mt = 0; mt < 4; mt++)
            #pragma unroll
            for (int nt = 0; nt < 4; nt++) {
                MMA_BF16(acc[mt][nt], af[mt], bhi[nt]);   // hi*hi
                MMA_BF16(acc[mt][nt], af[mt], blo[nt]);   // hi*lo
            }
        #pragma unroll
        for (int mt = 0; mt < 4; mt++) {
            const uint32_t off = (uint32_t)((wm*64 + mt*16 + lrow)*ROWP + lcol) * 2;
            LDSM4(af[mt][0], af[mt][1], af[mt][2], af[mt][3], base_al + off);
        }
        #pragma unroll
        for (int mt = 0; mt < 4; mt++)
            #pragma unroll
            for (int nt = 0; nt < 4; nt++)
                MMA_BF16(acc[mt][nt], af[mt], bhi[nt]);   // lo*hi

        // ---- convert + store prefetch into stage s^1 ----
        if (pf) {
            const int ns = s ^ 1;
            uint32_t h[4], l[4];
            split2(av0.x, av0.y, h[0], l[0]); split2(av0.z, av0.w, h[1], l[1]);
            split2(av1.x, av1.y, h[2], l[2]); split2(av1.z, av1.w, h[3], l[3]);
            *(uint4*)&pl[ns][0][arow*ROWP + akq] = make_uint4(h[0], h[1], h[2], h[3]);
            *(uint4*)&pl[ns][1][arow*ROWP + akq] = make_uint4(l[0], l[1], l[2], l[3]);
            const float bx[8] = {bv0.x, bv0.y, bv0.z, bv0.w, bv1.x, bv1.y, bv1.z, bv1.w};
            #pragma unroll
            for (int u = 0; u < 4; u++) {
                uint16_t hh, ll;
                splitf(bx[u], hh, ll);
                pl[ns][2][(bc0 + u)*ROWP + br0] = hh;
                pl[ns][3][(bc0 + u)*ROWP + br0] = ll;
                splitf(bx[4 + u], hh, ll);
                pl[ns][2][(bc1 + u)*ROWP + br1] = hh;
                pl[ns][3][(bc1 + u)*ROWP + br1] = ll;
            }
        }
        __syncthreads();
    }

    // ---- epilogue ----
    const int gid = lane >> 2, tig = lane & 3;
    #pragma unroll
    for (int mt = 0; mt < 4; mt++)
        #pragma unroll
        for (int nt = 0; nt < 4; nt++) {
            const int mr = m0 + wm*64 + mt*16 + gid;
            const int nc = n0 + wn*32 + nt*8 + 2*tig;
            emit<MODE>(mr,     nc,     acc[mt][nt][0], bias, out);
            emit<MODE>(mr,     nc + 1, acc[mt][nt][1], bias, out);
            emit<MODE>(mr + 8, nc,     acc[mt][nt][2], bias, out);
            emit<MODE>(mr + 8, nc + 1, acc[mt][nt][3], bias, out);
        }
}

// ---------------------------------------------------------------------------
// Flash attention (fp32): unchanged from round 2 (next round's target).
// ---------------------------------------------------------------------------
__global__ void __launch_bounds__(256) attn_kernel() {
    extern __shared__ __align__(16) float sm[];
    float* Qs = sm;                 // [128][64]
    float* Ks = Qs + 128*64;        // [64][65]
    float* Vt = Ks + 64*65;         // [64][65] transposed
    float* Ps = Vt + 64*65;         // [128][64]
    const int tid = threadIdx.x;
    const int tx = tid & 15, ty = tid >> 4;
    const int qi = gridDim.x - 1 - blockIdx.x;   // heavy tiles first
    const int bh = blockIdx.y;

    const float* Qg = g_Q + ((size_t)bh * T_ + qi * 128) * HD_;
    const float* Kg = g_K + (size_t)bh * T_ * HD_;
    const float* Vg = g_V + (size_t)bh * T_ * HD_;

    #pragma unroll
    for (int it = 0; it < 8; it++) {
        const int i = tid + it * 256;
        ((float4*)Qs)[i] = ((const float4*)Qg)[i];
    }

    float m_i[8], l_i[8], O[8][4];
    #pragma unroll
    for (int i = 0; i < 8; i++) {
        m_i[i] = -1e30f; l_i[i] = 0.0f;
        #pragma unroll
        for (int j = 0; j < 4; j++) O[i][j] = 0.0f;
    }

    const int ktEnd = 2 * qi + 1;
    for (int kt = 0; kt <= ktEnd; kt++) {
        __syncthreads();
        const float* K0 = Kg + (size_t)kt * 64 * HD_;
        const float* V0 = Vg + (size_t)kt * 64 * HD_;
        #pragma unroll
        for (int it = 0; it < 4; it++) {
            const int i = tid + it * 256;
            const int r  = i >> 4;
            const int dq = (i & 15) << 2;
            const float4 kv = *(const float4*)(K0 + r * HD_ + dq);
            float* kd = Ks + r * 65 + dq;
            kd[0] = kv.x; kd[1] = kv.y; kd[2] = kv.z; kd[3] = kv.w;
            const float4 vv = *(const float4*)(V0 + r * HD_ + dq);
            Vt[(dq+0)*65 + r] = vv.x;
            Vt[(dq+1)*65 + r] = vv.y;
            Vt[(dq+2)*65 + r] = vv.z;
            Vt[(dq+3)*65 + r] = vv.w;
        }
        __syncthreads();

        float S[8][4] = {};
        #pragma unroll 4
        for (int d4 = 0; d4 < 16; d4++) {
            float b_[4][4];
            #pragma unroll
            for (int dd = 0; dd < 4; dd++)
                #pragma unroll
                for (int j = 0; j < 4; j++)
                    b_[dd][j] = Ks[(4*tx+j)*65 + d4*4 + dd];
            #pragma unroll
            for (int g = 0; g < 2; g++) {
                #pragma unroll
                for (int i = 0; i < 4; i++) {
                    float a_[4];
                    *(float4*)a_ = *(const float4*)(Qs + (g*64 + 4*ty + i)*64 + d4*4);
                    #pragma unroll
                    for (int dd = 0; dd < 4; dd++)
                        #pragma unroll
                        for (int j = 0; j < 4; j++)
                            S[g*4+i][j] = fmaf(a_[dd], b_[dd][j], S[g*4+i][j]);
                }
            }
        }

        if (kt >= 2*qi) {
            #pragma unroll
            for (int g = 0; g < 2; g++)
                #pragma unroll
                for (int i = 0; i < 4; i++)
                    #pragma unroll
                    for (int j = 0; j < 4; j++) {
                        const int r = qi*128 + g*64 + 4*ty + i;
                        const int c = kt*64 + 4*tx + j;
                        if (c > r) S[g*4+i][j] = -1e30f;
                    }
        }

        #pragma unroll
        for (int ii = 0; ii < 8; ii++) {
            float rm = fmaxf(fmaxf(S[ii][0], S[ii][1]), fmaxf(S[ii][2], S[ii][3]));
            #pragma unroll
            for (int s = 8; s >= 1; s >>= 1)
                rm = fmaxf(rm, __shfl_xor_sync(0xffffffffu, rm, s));
            const float mn = fmaxf(m_i[ii], rm);
            const float corr = __expf(m_i[ii] - mn);
            m_i[ii] = mn;
            float rs = 0.0f;
            #pragma unroll
            for (int j = 0; j < 4; j++) { S[ii][j] = __expf(S[ii][j] - mn); rs += S[ii][j]; }
            #pragma unroll
            for (int s = 8; s >= 1; s >>= 1)
                rs += __shfl_xor_sync(0xffffffffu, rs, s);
            l_i[ii] = l_i[ii] * corr + rs;
            #pragma unroll
            for (int j = 0; j < 4; j++) O[ii][j] *= corr;
        }

        #pragma unroll
        for (int g = 0; g < 2; g++)
            #pragma unroll
            for (int i = 0; i < 4; i++) {
                float4 pv = make_float4(S[g*4+i][0], S[g*4+i][1], S[g*4+i][2], S[g*4+i][3]);
                *(float4*)(Ps + (g*64 + 4*ty + i)*64 + 4*tx) = pv;
            }
        __syncthreads();

        #pragma unroll 4
        for (int k4 = 0; k4 < 16; k4++) {
            float v_[4][4];
            #pragma unroll
            for (int kk = 0; kk < 4; kk++)
                #pragma unroll
                for (int j = 0; j < 4; j++)
                    v_[kk][j] = Vt[(4*tx+j)*65 + k4*4 + kk];
            #pragma unroll
            for (int g = 0; g < 2; g++) {
                #pragma unroll
                for (int i = 0; i < 4; i++) {
                    float p_[4];
                    *(float4*)p_ = *(const float4*)(Ps + (g*64 + 4*ty + i)*64 + k4*4);
                    #pragma unroll
                    for (int kk = 0; kk < 4; kk++)
                        #pragma unroll
                        for (int j = 0; j < 4; j++)
                            O[g*4+i][j] = fmaf(p_[kk], v_[kk][j], O[g*4+i][j]);
                }
            }
        }
    }

    const int b = bh >> 4, h = bh & 15;
    #pragma unroll
    for (int g = 0; g < 2; g++)
        #pragma unroll
        for (int i = 0; i < 4; i++) {
            const int ii = g*4 + i;
            const float inv = 1.0f / l_i[ii];
            const int t = qi*128 + g*64 + 4*ty + i;
            float* yp = g_Y + ((size_t)(b * T_ + t)) * C_ + h * HD_ + 4*tx;
            #pragma unroll
            for (int j = 0; j < 4; j++) yp[j] = O[ii][j] * inv;
        }
}

static const int ATTN_SMEM = (128*64 + 64*65 + 64*65 + 128*64) * (int)sizeof(float); // 98816 B

extern "C" void kernel_launch(void* const* d_in, const int* in_sizes, int n_in,
                              void* d_out, int out_size) {
    const float* x      = (const float*)d_in[0];
    const float* W_attn = (const float*)d_in[1];
    const float* b_attn = (const float*)d_in[2];
    const float* W_proj = (const float*)d_in[3];
    const float* b_proj = (const float*)d_in[4];
    float* out = (float*)d_out;

    cudaFuncSetAttribute(gemm_bf16<3*C_, 0>, cudaFuncAttributeMaxDynamicSharedMemorySize, GEMM_SMEM);
    cudaFuncSetAttribute(gemm_bf16<C_, 1>,   cudaFuncAttributeMaxDynamicSharedMemorySize, GEMM_SMEM);
    cudaFuncSetAttribute(attn_kernel, cudaFuncAttributeMaxDynamicSharedMemorySize, ATTN_SMEM);

    gemm_bf16<3*C_, 0><<<dim3(3*C_/128, M_/128), 256, GEMM_SMEM>>>(x, W_attn, b_attn, nullptr);
    attn_kernel<<<dim3(T_/128, NBH_), 256, ATTN_SMEM>>>();
    gemm_bf16<C_, 1><<<dim3(C_/128, M_/128), 256, GEMM_SMEM>>>(nullptr, W_proj, b_proj, out);
}

// round 4
// speedup vs baseline: 1.4446x; 1.4446x over previous
#include <cuda_runtime.h>
#include <cuda_bf16.h>
#include <cstdint>
#include <math.h>

#define B_  2
#define T_  2048
#define C_  1024
#define H_  16
#define HD_ 64
#define NBH_ (B_*H_)     // 32
#define M_   (B_*T_)     // 4096

// Scratch (allocation-free: __device__ globals)
__device__ float g_Q[(size_t)NBH_ * T_ * HD_];
__device__ float g_K[(size_t)NBH_ * T_ * HD_];
__device__ float g_V[(size_t)NBH_ * T_ * HD_];
__device__ float g_Y[(size_t)M_ * C_];

// Pre-split bf16 operands
__device__ __nv_bfloat16 g_xhi[(size_t)M_ * C_],     g_xlo[(size_t)M_ * C_];
__device__ __nv_bfloat16 g_yhi[(size_t)M_ * C_],     g_ylo[(size_t)M_ * C_];
__device__ __nv_bfloat16 g_wahi[(size_t)3*C_ * C_],  g_walo[(size_t)3*C_ * C_]; // Wt[n][k]
__device__ __nv_bfloat16 g_wphi[(size_t)C_ * C_],    g_wplo[(size_t)C_ * C_];   // Wt[n][k]

// ---------------------------------------------------------------------------
// helpers
// ---------------------------------------------------------------------------
__device__ __forceinline__ void splitf(float x, uint16_t& h, uint16_t& l) {
    __nv_bfloat16 hb = __float2bfloat16(x);
    __nv_bfloat16 lb = __float2bfloat16(x - __bfloat162float(hb));
    h = *reinterpret_cast<uint16_t*>(&hb);
    l = *reinterpret_cast<uint16_t*>(&lb);
}

#define LDSM4(r0, r1, r2, r3, addr) \
    asm volatile("ldmatrix.sync.aligned.m8n8.x4.shared.b16 {%0,%1,%2,%3}, [%4];" \
        : "=r"(r0), "=r"(r1), "=r"(r2), "=r"(r3) : "r"(addr))

#define MMA_BF16(d, a, b) \
    asm volatile("mma.sync.aligned.m16n8k16.row.col.f32.bf16.bf16.f32 " \
        "{%0,%1,%2,%3},{%4,%5,%6,%7},{%8,%9},{%0,%1,%2,%3};" \
        : "+f"((d)[0]), "+f"((d)[1]), "+f"((d)[2]), "+f"((d)[3]) \
        : "r"((a)[0]), "r"((a)[1]), "r"((a)[2]), "r"((a)[3]), \
          "r"((b)[0]), "r"((b)[1]))

__device__ __forceinline__ void cp16(uint32_t dst, const void* src) {
    asm volatile("cp.async.cg.shared.global [%0], [%1], 16;" :: "r"(dst), "l"(src));
}
#define CP_COMMIT() asm volatile("cp.async.commit_group;")

// ---------------------------------------------------------------------------
// Converters
// ---------------------------------------------------------------------------
__global__ void __launch_bounds__(256) split_f4(const float* __restrict__ src,
                                                __nv_bfloat16* __restrict__ hi,
                                                __nv_bfloat16* __restrict__ lo) {
    const int i = blockIdx.x * 256 + threadIdx.x;
    const float4 v = ((const float4*)src)[i];
    uint16_t h[4], l[4];
    splitf(v.x, h[0], l[0]); splitf(v.y, h[1], l[1]);
    splitf(v.z, h[2], l[2]); splitf(v.w, h[3], l[3]);
    uint2 uh = make_uint2((uint32_t)h[0] | ((uint32_t)h[1] << 16),
                          (uint32_t)h[2] | ((uint32_t)h[3] << 16));
    uint2 ul = make_uint2((uint32_t)l[0] | ((uint32_t)l[1] << 16),
                          (uint32_t)l[2] | ((uint32_t)l[3] << 16));
    ((uint2*)hi)[i] = uh;
    ((uint2*)lo)[i] = ul;
}

// W[1024][NC] -> Wt_hi/lo[NC][1024] (transposed, split)
template<int NC>
__global__ void __launch_bounds__(256) split_wt(const float* __restrict__ W,
                                                __nv_bfloat16* __restrict__ th,
                                                __nv_bfloat16* __restrict__ tl) {
    __shared__ float tile[32][33];
    const int n0 = blockIdx.x * 32, k0 = blockIdx.y * 32;
    const int tx = threadIdx.x & 31, ty = threadIdx.x >> 5;   // 32 x 8
    #pragma unroll
    for (int r = ty; r < 32; r += 8)
        tile[r][tx] = W[(size_t)(k0 + r) * NC + n0 + tx];
    __syncthreads();
    #pragma unroll
    for (int r = ty; r < 32; r += 8) {
        const float v = tile[tx][r];             // = W[k0+tx][n0+r]
        uint16_t h, l;
        splitf(v, h, l);
        th[(size_t)(n0 + r) * 1024 + k0 + tx] = *(__nv_bfloat16*)&h;
        tl[(size_t)(n0 + r) * 1024 + k0 + tx] = *(__nv_bfloat16*)&l;
    }
}

// ---------------------------------------------------------------------------
// Epilogue scatter
// ---------------------------------------------------------------------------
template<int MODE>
__device__ __forceinline__ void emit(int m, int n, float val,
                                     const float* __restrict__ bias,
                                     float* __restrict__ out) {
    val += bias[n];
    if (MODE == 0) {
        const int bb = m >> 11;
        const int t  = m & 2047;
        if (n < C_) {
            const int h = n >> 6, d = n & 63;
            g_Q[(((size_t)(bb*H_ + h))*T_ + t)*HD_ + d] = val * 0.125f;
        } else if (n < 2*C_) {
            const int nn = n - C_;
            const int h = nn >> 6, d = nn & 63;
            g_K[(((size_t)(bb*H_ + h))*T_ + t)*HD_ + d] = val;
        } else {
            const int nn = n - 2*C_;
            const int h = nn >> 6, d = nn & 63;
            g_V[(((size_t)(bb*H_ + h))*T_ + t)*HD_ + d] = val;
        }
    } else {
        out[(size_t)m * C_ + n] = val;
    }
}

// ---------------------------------------------------------------------------
// Tensor-core GEMM, pre-split bf16 operands (3-term), cp.async 3-stage pipeline
//   C[M,*] = A[M,1024] @ Bt[n][k]^T + bias
// CTA 128x128, 8 warps (2x4), warp tile 64x32, k-chunk 16.
// smem stage: 4 planes (Ahi,Alo,Bhi,Blo) of [128][24] bf16 (pad-24 rows:
// verified conflict-free for ldmatrix, 16B-aligned halves for cp.async).
// ---------------------------------------------------------------------------
#define ROWP 24
#define PLANE16 (128*ROWP)                 // uint16 per plane
#define STG16   (4*PLANE16)                // uint16 per stage
static const int GEMM_SMEM = 3 * STG16 * (int)sizeof(uint16_t);  // 73728 B

template<int MODE>
__global__ void __launch_bounds__(256) gemm_bf16s(const __nv_bfloat16* __restrict__ Ahi,
                                                  const __nv_bfloat16* __restrict__ Alo,
                                                  const __nv_bfloat16* __restrict__ Bhi,
                                                  const __nv_bfloat16* __restrict__ Blo,
                                                  const float* __restrict__ bias,
                                                  float* __restrict__ out) {
    extern __shared__ __align__(16) uint16_t sm16[];
    const int tid  = threadIdx.x;
    const int lane = tid & 31, wid = tid >> 5;
    const int wm = wid >> 2, wn = wid & 3;
    const int m0 = blockIdx.y * 128, n0 = blockIdx.x * 128;

    const uint32_t sm_base = (uint32_t)__cvta_generic_to_shared(sm16);

    // loader: each thread owns (row, k-half); 4x cp.async 16B per stage
    const int row = tid >> 1;
    const int half = (tid & 1) * 8;                    // k offset in elements
    const __nv_bfloat16* pAhi = Ahi + (size_t)(m0 + row) * 1024 + half;
    const __nv_bfloat16* pAlo = Alo + (size_t)(m0 + row) * 1024 + half;
    const __nv_bfloat16* pBhi = Bhi + (size_t)(n0 + row) * 1024 + half;
    const __nv_bfloat16* pBlo = Blo + (size_t)(n0 + row) * 1024 + half;
    const uint32_t dst_off = (uint32_t)(row * ROWP + half) * 2;

    auto issue = [&](int stage, int k0) {
        const uint32_t b = sm_base + (uint32_t)stage * STG16 * 2 + dst_off;
        cp16(b + 0u * PLANE16 * 2, pAhi + k0);
        cp16(b + 1u * PLANE16 * 2, pAlo + k0);
        cp16(b + 2u * PLANE16 * 2, pBhi + k0);
        cp16(b + 3u * PLANE16 * 2, pBlo + k0);
        CP_COMMIT();
    };

    float acc[4][4][4];
    #pragma unroll
    for (int mt = 0; mt < 4; mt++)
        #pragma unroll
        for (int nt = 0; nt < 4; nt++)
            #pragma unroll
            for (int e = 0; e < 4; e++) acc[mt][nt][e] = 0.0f;

    const int lrow = lane & 15, lcol = (lane >> 4) * 8;

    issue(0, 0);
    issue(1, 16);

    for (int it = 0; it < 64; it++) {
        if (it < 63) asm volatile("cp.async.wait_group 1;");
        else         asm volatile("cp.async.wait_group 0;");
        __syncthreads();

        const int s = it - (it / 3) * 3;    // it % 3
        const uint32_t base_ah = sm_base + (uint32_t)(s * STG16 + 0 * PLANE16) * 2;
        const uint32_t base_al = sm_base + (uint32_t)(s * STG16 + 1 * PLANE16) * 2;
        const uint32_t base_bh = sm_base + (uint32_t)(s * STG16 + 2 * PLANE16) * 2;
        const uint32_t base_bl = sm_base + (uint32_t)(s * STG16 + 3 * PLANE16) * 2;

        uint32_t bhi[4][2], blo[4][2];
        #pragma unroll
        for (int j = 0; j < 2; j++) {
            const uint32_t off = (uint32_t)((wn*32 + j*16 + lrow) * ROWP + lcol) * 2;
            uint32_t r0, r1, r2, r3;
            LDSM4(r0, r1, r2, r3, base_bh + off);
            bhi[2*j][0] = r0; bhi[2*j][1] = r2;
            bhi[2*j+1][0] = r1; bhi[2*j+1][1] = r3;
            LDSM4(r0, r1, r2, r3, base_bl + off);
            blo[2*j][0] = r0; blo[2*j][1] = r2;
            blo[2*j+1][0] = r1; blo[2*j+1][1] = r3;
        }

        uint32_t af[4][4];
        #pragma unroll
        for (int mt = 0; mt < 4; mt++) {
            const uint32_t off = (uint32_t)((wm*64 + mt*16 + lrow) * ROWP + lcol) * 2;
            LDSM4(af[mt][0], af[mt][1], af[mt][2], af[mt][3], base_ah + off);
        }
        #pragma unroll
        for (int mt = 0; mt < 4; mt++)
            #pragma unroll
            for (int nt = 0; nt < 4; nt++) {
                MMA_BF16(acc[mt][nt], af[mt], bhi[nt]);   // hi*hi
                MMA_BF16(acc[mt][nt], af[mt], blo[nt]);   // hi*lo
            }
        #pragma unroll
        for (int mt = 0; mt < 4; mt++) {
            const uint32_t off = (uint32_t)((wm*64 + mt*16 + lrow) * ROWP + lcol) * 2;
            LDSM4(af[mt][0], af[mt][1], af[mt][2], af[mt][3], base_al + off);
        }
        #pragma unroll
        for (int mt = 0; mt < 4; mt++)
            #pragma unroll
            for (int nt = 0; nt < 4; nt++)
                MMA_BF16(acc[mt][nt], af[mt], bhi[nt]);   // lo*hi

        if (it + 2 < 64) {
            const int ns = (it + 2) - ((it + 2) / 3) * 3;
            issue(ns, (it + 2) * 16);
        }
    }

    const int gid = lane >> 2, tig = lane & 3;
    #pragma unroll
    for (int mt = 0; mt < 4; mt++)
        #pragma unroll
        for (int nt = 0; nt < 4; nt++) {
            const int mr = m0 + wm*64 + mt*16 + gid;
            const int nc = n0 + wn*32 + nt*8 + 2*tig;
            emit<MODE>(mr,     nc,     acc[mt][nt][0], bias, out);
            emit<MODE>(mr,     nc + 1, acc[mt][nt][1], bias, out);
            emit<MODE>(mr + 8, nc,     acc[mt][nt][2], bias, out);
            emit<MODE>(mr + 8, nc + 1, acc[mt][nt][3], bias, out);
        }
}

// ---------------------------------------------------------------------------
// Flash attention (fp32): unchanged (next round's target).
// ---------------------------------------------------------------------------
__global__ void __launch_bounds__(256) attn_kernel() {
    extern __shared__ __align__(16) float sm[];
    float* Qs = sm;                 // [128][64]
    float* Ks = Qs + 128*64;        // [64][65]
    float* Vt = Ks + 64*65;         // [64][65] transposed
    float* Ps = Vt + 64*65;         // [128][64]
    const int tid = threadIdx.x;
    const int tx = tid & 15, ty = tid >> 4;
    const int qi = gridDim.x - 1 - blockIdx.x;
    const int bh = blockIdx.y;

    const float* Qg = g_Q + ((size_t)bh * T_ + qi * 128) * HD_;
    const float* Kg = g_K + (size_t)bh * T_ * HD_;
    const float* Vg = g_V + (size_t)bh * T_ * HD_;

    #pragma unroll
    for (int it = 0; it < 8; it++) {
        const int i = tid + it * 256;
        ((float4*)Qs)[i] = ((const float4*)Qg)[i];
    }

    float m_i[8], l_i[8], O[8][4];
    #pragma unroll
    for (int i = 0; i < 8; i++) {
        m_i[i] = -1e30f; l_i[i] = 0.0f;
        #pragma unroll
        for (int j = 0; j < 4; j++) O[i][j] = 0.0f;
    }

    const int ktEnd = 2 * qi + 1;
    for (int kt = 0; kt <= ktEnd; kt++) {
        __syncthreads();
        const float* K0 = Kg + (size_t)kt * 64 * HD_;
        const float* V0 = Vg + (size_t)kt * 64 * HD_;
        #pragma unroll
        for (int it = 0; it < 4; it++) {
            const int i = tid + it * 256;
            const int r  = i >> 4;
            const int dq = (i & 15) << 2;
            const float4 kv = *(const float4*)(K0 + r * HD_ + dq);
            float* kd = Ks + r * 65 + dq;
            kd[0] = kv.x; kd[1] = kv.y; kd[2] = kv.z; kd[3] = kv.w;
            const float4 vv = *(const float4*)(V0 + r * HD_ + dq);
            Vt[(dq+0)*65 + r] = vv.x;
            Vt[(dq+1)*65 + r] = vv.y;
            Vt[(dq+2)*65 + r] = vv.z;
            Vt[(dq+3)*65 + r] = vv.w;
        }
        __syncthreads();

        float S[8][4] = {};
        #pragma unroll 4
        for (int d4 = 0; d4 < 16; d4++) {
            float b_[4][4];
            #pragma unroll
            for (int dd = 0; dd < 4; dd++)
                #pragma unroll
                for (int j = 0; j < 4; j++)
                    b_[dd][j] = Ks[(4*tx+j)*65 + d4*4 + dd];
            #pragma unroll
            for (int g = 0; g < 2; g++) {
                #pragma unroll
                for (int i = 0; i < 4; i++) {
                    float a_[4];
                    *(float4*)a_ = *(const float4*)(Qs + (g*64 + 4*ty + i)*64 + d4*4);
                    #pragma unroll
                    for (int dd = 0; dd < 4; dd++)
                        #pragma unroll
                        for (int j = 0; j < 4; j++)
                            S[g*4+i][j] = fmaf(a_[dd], b_[dd][j], S[g*4+i][j]);
                }
            }
        }

        if (kt >= 2*qi) {
            #pragma unroll
            for (int g = 0; g < 2; g++)
                #pragma unroll
                for (int i = 0; i < 4; i++)
                    #pragma unroll
                    for (int j = 0; j < 4; j++) {
                        const int r = qi*128 + g*64 + 4*ty + i;
                        const int c = kt*64 + 4*tx + j;
                        if (c > r) S[g*4+i][j] = -1e30f;
                    }
        }

        #pragma unroll
        for (int ii = 0; ii < 8; ii++) {
            float rm = fmaxf(fmaxf(S[ii][0], S[ii][1]), fmaxf(S[ii][2], S[ii][3]));
            #pragma unroll
            for (int s = 8; s >= 1; s >>= 1)
                rm = fmaxf(rm, __shfl_xor_sync(0xffffffffu, rm, s));
            const float mn = fmaxf(m_i[ii], rm);
            const float corr = __expf(m_i[ii] - mn);
            m_i[ii] = mn;
            float rs = 0.0f;
            #pragma unroll
            for (int j = 0; j < 4; j++) { S[ii][j] = __expf(S[ii][j] - mn); rs += S[ii][j]; }
            #pragma unroll
            for (int s = 8; s >= 1; s >>= 1)
                rs += __shfl_xor_sync(0xffffffffu, rs, s);
            l_i[ii] = l_i[ii] * corr + rs;
            #pragma unroll
            for (int j = 0; j < 4; j++) O[ii][j] *= corr;
        }

        #pragma unroll
        for (int g = 0; g < 2; g++)
            #pragma unroll
            for (int i = 0; i < 4; i++) {
                float4 pv = make_float4(S[g*4+i][0], S[g*4+i][1], S[g*4+i][2], S[g*4+i][3]);
                *(float4*)(Ps + (g*64 + 4*ty + i)*64 + 4*tx) = pv;
            }
        __syncthreads();

        #pragma unroll 4
        for (int k4 = 0; k4 < 16; k4++) {
            float v_[4][4];
            #pragma unroll
            for (int kk = 0; kk < 4; kk++)
                #pragma unroll
                for (int j = 0; j < 4; j++)
                    v_[kk][j] = Vt[(4*tx+j)*65 + k4*4 + kk];
            #pragma unroll
            for (int g = 0; g < 2; g++) {
                #pragma unroll
                for (int i = 0; i < 4; i++) {
                    float p_[4];
                    *(float4*)p_ = *(const float4*)(Ps + (g*64 + 4*ty + i)*64 + k4*4);
                    #pragma unroll
                    for (int kk = 0; kk < 4; kk++)
                        #pragma unroll
                        for (int j = 0; j < 4; j++)
                            O[g*4+i][j] = fmaf(p_[kk], v_[kk][j], O[g*4+i][j]);
                }
            }
        }
    }

    const int b = bh >> 4, h = bh & 15;
    #pragma unroll
    for (int g = 0; g < 2; g++)
        #pragma unroll
        for (int i = 0; i < 4; i++) {
            const int ii = g*4 + i;
            const float inv = 1.0f / l_i[ii];
            const int t = qi*128 + g*64 + 4*ty + i;
            float* yp = g_Y + ((size_t)(b * T_ + t)) * C_ + h * HD_ + 4*tx;
            #pragma unroll
            for (int j = 0; j < 4; j++) yp[j] = O[ii][j] * inv;
        }
}

static const int ATTN_SMEM = (128*64 + 64*65 + 64*65 + 128*64) * (int)sizeof(float); // 98816 B

extern "C" void kernel_launch(void* const* d_in, const int* in_sizes, int n_in,
                              void* d_out, int out_size) {
    const float* x      = (const float*)d_in[0];
    const float* W_attn = (const float*)d_in[1];
    const float* b_attn = (const float*)d_in[2];
    const float* W_proj = (const float*)d_in[3];
    const float* b_proj = (const float*)d_in[4];
    float* out = (float*)d_out;

    cudaFuncSetAttribute(gemm_bf16s<0>, cudaFuncAttributeMaxDynamicSharedMemorySize, GEMM_SMEM);
    cudaFuncSetAttribute(gemm_bf16s<1>, cudaFuncAttributeMaxDynamicSharedMemorySize, GEMM_SMEM);
    cudaFuncSetAttribute(attn_kernel,   cudaFuncAttributeMaxDynamicSharedMemorySize, ATTN_SMEM);

    __nv_bfloat16 *xhi, *xlo, *yhi, *ylo, *wahi, *walo, *wphi, *wplo;
    cudaGetSymbolAddress((void**)&xhi,  g_xhi);  cudaGetSymbolAddress((void**)&xlo,  g_xlo);
    cudaGetSymbolAddress((void**)&yhi,  g_yhi);  cudaGetSymbolAddress((void**)&ylo,  g_ylo);
    cudaGetSymbolAddress((void**)&wahi, g_wahi); cudaGetSymbolAddress((void**)&walo, g_walo);
    cudaGetSymbolAddress((void**)&wphi, g_wphi); cudaGetSymbolAddress((void**)&wplo, g_wplo);
    float* yf;
    cudaGetSymbolAddress((void**)&yf, g_Y);

    // converters
    split_f4<<<(M_*C_/4)/256, 256>>>(x, xhi, xlo);
    split_wt<3*C_><<<dim3(3*C_/32, C_/32), 256>>>(W_attn, wahi, walo);
    split_wt<C_><<<dim3(C_/32, C_/32), 256>>>(W_proj, wphi, wplo);

    // qkv
    gemm_bf16s<0><<<dim3(3*C_/128, M_/128), 256, GEMM_SMEM>>>(xhi, xlo, wahi, walo, b_attn, nullptr);
    // attention
    attn_kernel<<<dim3(T_/128, NBH_), 256, ATTN_SMEM>>>();
    // split Y, then proj
    split_f4<<<(M_*C_/4)/256, 256>>>(yf, yhi, ylo);
    gemm_bf16s<1><<<dim3(C_/128, M_/128), 256, GEMM_SMEM>>>(yhi, ylo, wphi, wplo, b_proj, out);
}